// round 7
// baseline (speedup 1.0000x reference)
#include <cuda_runtime.h>

#ifndef BATCH_THREADS
#define BATCH_THREADS 256
#endif

__global__ void __launch_bounds__(BATCH_THREADS, 6)
transop_expm_kernel(const float* __restrict__ c,
                    const float* __restrict__ x,
                    const float* __restrict__ psi,
                    float* __restrict__ out,
                    int B) {
    // psi transposed: sp_t[p*8 + m] = psi[m*9 + p]  (rows padded to 8 floats
    // so each row is one LDS.128 + one LDS.64, 32B-aligned)
    __shared__ float sp_t[72];
    if (threadIdx.x < 54) {
        int m = threadIdx.x / 9;
        int p = threadIdx.x % 9;
        sp_t[p * 8 + m] = psi[threadIdx.x];
    }
    __syncthreads();

    int b = blockIdx.x * BATCH_THREADS + threadIdx.x;
    if (b >= B) return;

    // ---- c[b,0..5] : three float2 loads (aligned: 6*b even) ----
    const float2* c2 = reinterpret_cast<const float2*>(c);
    float2 ca = c2[3 * b + 0];
    float2 cb = c2[3 * b + 1];
    float2 cd = c2[3 * b + 2];
    float cc0 = ca.x, cc1 = ca.y, cc2 = cb.x, cc3 = cb.y, cc4 = cd.x, cc5 = cd.y;

    // ---- T = sum_m cc[m] * psi[m]  (54 FMA, 18 vector LDS) ----
    float T[9];
#pragma unroll
    for (int p = 0; p < 9; p++) {
        float4 a4 = *reinterpret_cast<const float4*>(&sp_t[p * 8]);
        float2 a2 = *reinterpret_cast<const float2*>(&sp_t[p * 8 + 4]);
        float s = cc0 * a4.x;
        s = fmaf(cc1, a4.y, s);
        s = fmaf(cc2, a4.z, s);
        s = fmaf(cc3, a4.w, s);
        s = fmaf(cc4, a2.x, s);
        s = fmaf(cc5, a2.y, s);
        T[p] = s;
    }

    // ---- split: T = mu*I + T0 (traceless) ----
    float mu = (T[0] + T[4] + T[8]) * (1.0f / 3.0f);
    T[0] -= mu;
    T[4] -= mu;
    T[8] -= mu;

    // ---- char poly of T0:  T0^3 = p*T0 + q*I ----
    float u = T[0] * T[0];
    u = fmaf(T[4], T[4], u);
    u = fmaf(T[8], T[8], u);
    float v = T[1] * T[3];
    v = fmaf(T[2], T[6], v);
    v = fmaf(T[5], T[7], v);
    float pc = fmaf(0.5f, u, v);

    float m0 = fmaf(T[4], T[8], -T[5] * T[7]);
    float m1 = fmaf(T[5], T[6], -T[3] * T[8]);
    float m2 = fmaf(T[3], T[7], -T[4] * T[6]);
    float qc = T[0] * m0;
    qc = fmaf(T[1], m1, qc);
    qc = fmaf(T[2], m2, qc);

    // ---- scale to Y = T0/8: pY = p/64, qY = q/512 ----
    float pY = pc * (1.0f / 64.0f);
    float qY = qc * (1.0f / 512.0f);

    // ---- exp(Y) mod (X^3 - pY X - qY), Horner deg-9:
    //   (s0,s1,s2)*X = (s2*qY, s0 + s2*pY, s1); S <- S*X + 1/k!
    float s0 = 1.0f / 362880.0f;  // 1/9!
    float s1 = 0.0f, s2 = 0.0f;
    const float w[9] = {1.0f,
                        1.0f,
                        1.0f / 2.0f,
                        1.0f / 6.0f,
                        1.0f / 24.0f,
                        1.0f / 120.0f,
                        1.0f / 720.0f,
                        1.0f / 5040.0f,
                        1.0f / 40320.0f};  // 1/k!, k=0..8
#pragma unroll
    for (int k = 8; k >= 0; k--) {
        float n0 = fmaf(s2, qY, w[k]);
        float n1 = fmaf(s2, pY, s0);
        s2 = s1;
        s0 = n0;
        s1 = n1;
    }

    // ---- 3 squarings in coefficient space: exp(2Y), exp(4Y), exp(8Y) ----
#pragma unroll
    for (int i = 0; i < 3; i++) {
        float d0 = s0 + s0;
        float b0 = s0 * s0;
        float b1 = d0 * s1;
        float b2 = fmaf(s1, s1, d0 * s2);
        float b3 = (s1 + s1) * s2;
        float b4 = s2 * s2;
        s0 = fmaf(qY, b3, b0);
        s1 = fmaf(pY, b3, fmaf(qY, b4, b1));
        s2 = fmaf(pY, b4, b2);
    }
    // exp(T0) = s0*I + s1*Y + s2*Y^2, Y = T0/8

    // ---- fold e^mu and basis scales ----
    float emu = __expf(mu);
    float g0 = s0 * emu;
    float g1 = s1 * emu * 0.125f;
    float g2 = s2 * emu * 0.015625f;

    // ---- y = g0*x + g1*(T0 x) + g2*(T0 (T0 x)) ----
    float x0 = x[3 * b + 0];
    float x1 = x[3 * b + 1];
    float x2 = x[3 * b + 2];

    float v0 = fmaf(T[0], x0, fmaf(T[1], x1, T[2] * x2));
    float v1 = fmaf(T[3], x0, fmaf(T[4], x1, T[5] * x2));
    float v2 = fmaf(T[6], x0, fmaf(T[7], x1, T[8] * x2));

    float w0 = fmaf(T[0], v0, fmaf(T[1], v1, T[2] * v2));
    float w1 = fmaf(T[3], v0, fmaf(T[4], v1, T[5] * v2));
    float w2 = fmaf(T[6], v0, fmaf(T[7], v1, T[8] * v2));

    float y0 = fmaf(g0, x0, fmaf(g1, v0, g2 * w0));
    float y1 = fmaf(g0, x1, fmaf(g1, v1, g2 * w1));
    float y2 = fmaf(g0, x2, fmaf(g1, v2, g2 * w2));

    out[3 * b + 0] = y0;
    out[3 * b + 1] = y1;
    out[3 * b + 2] = y2;
}

extern "C" void kernel_launch(void* const* d_in, const int* in_sizes, int n_in,
                              void* d_out, int out_size) {
    // Identify inputs by element count: psi=54, c=B*6, x=B*3
    const float* c = nullptr;
    const float* x = nullptr;
    const float* psi = nullptr;
    long long maxsz = 0;
    for (int i = 0; i < n_in; i++)
        if ((long long)in_sizes[i] > maxsz) maxsz = in_sizes[i];
    int B = (int)(maxsz / 6);
    for (int i = 0; i < n_in; i++) {
        if (in_sizes[i] == 54) psi = (const float*)d_in[i];
        else if (in_sizes[i] == B * 6) c = (const float*)d_in[i];
        else if (in_sizes[i] == B * 3) x = (const float*)d_in[i];
    }

    float* out = (float*)d_out;
    int grid = (B + BATCH_THREADS - 1) / BATCH_THREADS;
    transop_expm_kernel<<<grid, BATCH_THREADS>>>(c, x, psi, out, B);
}

// round 9
// speedup vs baseline: 1.0661x; 1.0661x over previous
#include <cuda_runtime.h>

#ifndef BATCH_THREADS
#define BATCH_THREADS 256
#endif

__global__ void __launch_bounds__(BATCH_THREADS, 4)
transop_expm_kernel(const float* __restrict__ c,
                    const float* __restrict__ x,
                    const float* __restrict__ psi,
                    float* __restrict__ out,
                    int B) {
    __shared__ float sp[54];
    if (threadIdx.x < 54) sp[threadIdx.x] = psi[threadIdx.x];
    __syncthreads();

    int t = blockIdx.x * BATCH_THREADS + threadIdx.x;  // items 2t, 2t+1
    if (2 * t >= B) return;

    // ---- c for both items: 12 contiguous floats = 3x LDG.128 ----
    const float4* c4 = reinterpret_cast<const float4*>(c);
    float4 A  = c4[3 * t + 0];
    float4 Bv = c4[3 * t + 1];
    float4 Cv = c4[3 * t + 2];
    float cc[2][6] = {{A.x, A.y, A.z, A.w, Bv.x, Bv.y},
                      {Bv.z, Bv.w, Cv.x, Cv.y, Cv.z, Cv.w}};

    // ---- T[i] = sum_m cc[i][m] * psi[m] (two independent chains) ----
    float T[2][9];
#pragma unroll
    for (int p = 0; p < 9; p++) {
        float w0 = sp[p];
        float w1 = sp[9 + p];
        float w2 = sp[18 + p];
        float w3 = sp[27 + p];
        float w4 = sp[36 + p];
        float w5 = sp[45 + p];
#pragma unroll
        for (int i = 0; i < 2; i++) {
            float s = cc[i][0] * w0;
            s = fmaf(cc[i][1], w1, s);
            s = fmaf(cc[i][2], w2, s);
            s = fmaf(cc[i][3], w3, s);
            s = fmaf(cc[i][4], w4, s);
            s = fmaf(cc[i][5], w5, s);
            T[i][p] = s;
        }
    }

    float g0[2], g1[2], g2[2];
#pragma unroll
    for (int i = 0; i < 2; i++) {
        // ---- split: T = mu*I + T0 (traceless) ----
        float mu = (T[i][0] + T[i][4] + T[i][8]) * (1.0f / 3.0f);
        T[i][0] -= mu;
        T[i][4] -= mu;
        T[i][8] -= mu;

        // ---- char poly: T0^3 = p*T0 + q*I ----
        float u = T[i][0] * T[i][0];
        u = fmaf(T[i][4], T[i][4], u);
        u = fmaf(T[i][8], T[i][8], u);
        float v = T[i][1] * T[i][3];
        v = fmaf(T[i][2], T[i][6], v);
        v = fmaf(T[i][5], T[i][7], v);
        float pc = fmaf(0.5f, u, v);

        float m0 = fmaf(T[i][4], T[i][8], -T[i][5] * T[i][7]);
        float m1 = fmaf(T[i][5], T[i][6], -T[i][3] * T[i][8]);
        float m2 = fmaf(T[i][3], T[i][7], -T[i][4] * T[i][6]);
        float qc = T[i][0] * m0;
        qc = fmaf(T[i][1], m1, qc);
        qc = fmaf(T[i][2], m2, qc);

        // Y = T0/8: pY = p/64, qY = q/512
        float pY = pc * (1.0f / 64.0f);
        float qY = qc * (1.0f / 512.0f);

        // ---- exp(Y) mod (X^3 - pY X - qY), Horner deg-9 ----
        float s0 = 1.0f / 362880.0f;  // 1/9!
        float s1 = 0.0f, s2 = 0.0f;
        const float w[9] = {1.0f,
                            1.0f,
                            1.0f / 2.0f,
                            1.0f / 6.0f,
                            1.0f / 24.0f,
                            1.0f / 120.0f,
                            1.0f / 720.0f,
                            1.0f / 5040.0f,
                            1.0f / 40320.0f};
#pragma unroll
        for (int k = 8; k >= 0; k--) {
            float n0 = fmaf(s2, qY, w[k]);
            float n1 = fmaf(s2, pY, s0);
            s2 = s1;
            s0 = n0;
            s1 = n1;
        }

        // ---- 3 squarings in coefficient space ----
#pragma unroll
        for (int j = 0; j < 3; j++) {
            float d0 = s0 + s0;
            float b0 = s0 * s0;
            float b1 = d0 * s1;
            float b2 = fmaf(s1, s1, d0 * s2);
            float b3 = (s1 + s1) * s2;
            float b4 = s2 * s2;
            s0 = fmaf(qY, b3, b0);
            s1 = fmaf(pY, b3, fmaf(qY, b4, b1));
            s2 = fmaf(pY, b4, b2);
        }

        // ---- fold e^mu and basis scales ----
        float emu = __expf(mu);
        g0[i] = s0 * emu;
        g1[i] = s1 * emu * 0.125f;
        g2[i] = s2 * emu * 0.015625f;
    }

    // ---- x loads for both items: 6 floats = 3x LDG.64 ----
    const float2* x2 = reinterpret_cast<const float2*>(x);
    float2 X0 = x2[3 * t + 0];  // xA0, xA1
    float2 X1 = x2[3 * t + 1];  // xA2, xB0
    float2 X2 = x2[3 * t + 2];  // xB1, xB2
    float xx[2][3] = {{X0.x, X0.y, X1.x}, {X1.y, X2.x, X2.y}};

    float yy[2][3];
#pragma unroll
    for (int i = 0; i < 2; i++) {
        float x0 = xx[i][0], x1 = xx[i][1], x2v = xx[i][2];
        float v0 = fmaf(T[i][0], x0, fmaf(T[i][1], x1, T[i][2] * x2v));
        float v1 = fmaf(T[i][3], x0, fmaf(T[i][4], x1, T[i][5] * x2v));
        float v2 = fmaf(T[i][6], x0, fmaf(T[i][7], x1, T[i][8] * x2v));

        float w0 = fmaf(T[i][0], v0, fmaf(T[i][1], v1, T[i][2] * v2));
        float w1 = fmaf(T[i][3], v0, fmaf(T[i][4], v1, T[i][5] * v2));
        float w2 = fmaf(T[i][6], v0, fmaf(T[i][7], v1, T[i][8] * v2));

        yy[i][0] = fmaf(g0[i], x0, fmaf(g1[i], v0, g2[i] * w0));
        yy[i][1] = fmaf(g0[i], x1, fmaf(g1[i], v1, g2[i] * w1));
        yy[i][2] = fmaf(g0[i], x2v, fmaf(g1[i], v2, g2[i] * w2));
    }

    float2* o2 = reinterpret_cast<float2*>(out);
    o2[3 * t + 0] = make_float2(yy[0][0], yy[0][1]);
    o2[3 * t + 1] = make_float2(yy[0][2], yy[1][0]);
    o2[3 * t + 2] = make_float2(yy[1][1], yy[1][2]);
}

extern "C" void kernel_launch(void* const* d_in, const int* in_sizes, int n_in,
                              void* d_out, int out_size) {
    // Identify inputs by element count: psi=54, c=B*6, x=B*3
    const float* c = nullptr;
    const float* x = nullptr;
    const float* psi = nullptr;
    long long maxsz = 0;
    for (int i = 0; i < n_in; i++)
        if ((long long)in_sizes[i] > maxsz) maxsz = in_sizes[i];
    int B = (int)(maxsz / 6);
    for (int i = 0; i < n_in; i++) {
        if (in_sizes[i] == 54) psi = (const float*)d_in[i];
        else if (in_sizes[i] == B * 6) c = (const float*)d_in[i];
        else if (in_sizes[i] == B * 3) x = (const float*)d_in[i];
    }

    float* out = (float*)d_out;
    int nthreads = (B + 1) / 2;  // 2 items per thread
    int grid = (nthreads + BATCH_THREADS - 1) / BATCH_THREADS;
    transop_expm_kernel<<<grid, BATCH_THREADS>>>(c, x, psi, out, B);
}